// round 7
// baseline (speedup 1.0000x reference)
#include <cuda_runtime.h>
#include <cuda_fp16.h>
#include <cstdint>

#define BB 8
#define NN 2048
#define FF 256
#define ALPHA 0.2f

// -------- scratch (device globals; no allocation allowed) --------
__device__ __half g_WhT_hi[BB * FF * NN];     // 8 MB  (Wh^T, fp16 high part)
__device__ __half g_WhT_lo[BB * FF * NN];     // 8 MB  (Wh^T, fp16 low part)
__device__ __half g_WT_hi[FF * FF];           // W^T fp16 hi  [f][k]
__device__ __half g_WT_lo[FF * FF];           // W^T fp16 lo
__device__ float g_s1[BB * NN];
__device__ float g_s2[BB * NN];
__device__ float g_s2max[BB];

// ============================================================
// common helpers
// ============================================================
__device__ __forceinline__ void mma16816(float* c, const uint32_t* a, const uint32_t* b)
{
    asm volatile(
        "mma.sync.aligned.m16n8k16.row.col.f32.f16.f16.f32 "
        "{%0,%1,%2,%3}, {%4,%5,%6,%7}, {%8,%9}, {%0,%1,%2,%3};"
        : "+f"(c[0]), "+f"(c[1]), "+f"(c[2]), "+f"(c[3])
        : "r"(a[0]), "r"(a[1]), "r"(a[2]), "r"(a[3]), "r"(b[0]), "r"(b[1]));
}
__device__ __forceinline__ void ldsm_x4(uint32_t* r, uint32_t addr)
{
    asm volatile("ldmatrix.sync.aligned.m8n8.x4.shared.b16 {%0,%1,%2,%3}, [%4];"
        : "=r"(r[0]), "=r"(r[1]), "=r"(r[2]), "=r"(r[3]) : "r"(addr));
}
__device__ __forceinline__ uint32_t smem_u32(const void* p) {
    uint32_t a;
    asm("{ .reg .u64 t; cvta.to.shared.u64 t, %1; cvt.u32.u64 %0, t; }" : "=r"(a) : "l"(p));
    return a;
}
#define CP_ASYNC16(dst, src) asm volatile("cp.async.cg.shared.global [%0], [%1], 16;" :: "r"(dst), "l"(src) : "memory")
#define CP_COMMIT()  asm volatile("cp.async.commit_group;" ::: "memory")
#define CP_WAIT0()   asm volatile("cp.async.wait_group 0;" ::: "memory")

#define VST 144   // smem row stride (64 fp16 + pad) -> conflict-free LDSM

// ============================================================
// Kernel 0: W [k][f] fp32 -> W^T hi/lo fp16 [f][k]
// ============================================================
__global__ __launch_bounds__(256) void prep_wt_kernel(const float* __restrict__ W)
{
    __shared__ float t[32][33];
    const int k0 = blockIdx.x * 32, f0 = blockIdx.y * 32;
    const int x = threadIdx.x & 31, y = threadIdx.x >> 5;
#pragma unroll
    for (int r = 0; r < 4; r++)
        t[y * 4 + r][x] = W[(size_t)(k0 + y * 4 + r) * FF + f0 + x];
    __syncthreads();
#pragma unroll
    for (int r = 0; r < 4; r++) {
        const int f = f0 + y * 4 + r;
        float v = t[x][y * 4 + r];
        __half hi = __float2half_rn(v);
        g_WT_hi[(size_t)f * FF + k0 + x] = hi;
        g_WT_lo[(size_t)f * FF + k0 + x] = __float2half_rn(v - __half2float(hi));
    }
}

// ============================================================
// Kernel 1: fused Wh GEMM (split-fp16 3-pass mma) + s1/s2 + WhT hi/lo
// (unchanged from R6)
// ============================================================
#define GS_BH 0
#define GS_BL (GS_BH + FF * VST)
#define GS_AH (GS_BL + FF * VST)
#define GS_AL (GS_AH + 64 * VST)
#define GS_S1P (GS_AL + 64 * VST)
#define GS_S2P (GS_S1P + 64 * 4)
#define GS_TOTAL (GS_S2P + 64 * 4)
#define TSTR 66

__global__ __launch_bounds__(256, 2) void gemm_fused_kernel(
    const float* __restrict__ h, const float* __restrict__ aVec)
{
    extern __shared__ char smem[];
    const uint32_t smem_base = smem_u32(smem);
    const int tid = threadIdx.x;
    const int wid = tid >> 5;
    const int lane = tid & 31;
    const int m0 = blockIdx.x * 64;
    const int b = m0 / NN;
    const int n_in_b = m0 - b * NN;

    const int m0w = (wid & 1) * 32;
    const int n0w = (wid >> 1) * 64;

    float acc[2][8][4];
#pragma unroll
    for (int mt = 0; mt < 2; mt++)
#pragma unroll
        for (int nt = 0; nt < 8; nt++)
#pragma unroll
            for (int q = 0; q < 4; q++) acc[mt][nt][q] = 0.f;

    const uint32_t a_off_h = smem_base + GS_AH
        + (uint32_t)(m0w + ((lane >> 3) & 1) * 8 + (lane & 7)) * VST
        + (uint32_t)(lane >> 4) * 16;
    const uint32_t a_off_l = a_off_h + (GS_AL - GS_AH);
    const uint32_t b_row = (uint32_t)(n0w + ((lane >> 4) & 1) * 8 + (lane & 7)) * VST
        + (uint32_t)((lane >> 3) & 1) * 16;

    for (int kt = 0; kt < 4; kt++) {
        const int k0 = kt * 64;
#pragma unroll
        for (int it = 0; it < 8; it++) {
            const int idx = tid + it * 256;
            const int f = idx >> 3;
            const int c = idx & 7;
            const uint32_t so = f * VST + c * 16;
            const size_t go = (size_t)f * FF + k0 + c * 8;
            CP_ASYNC16(smem_base + GS_BH + so, (const char*)(g_WT_hi + go));
            CP_ASYNC16(smem_base + GS_BL + so, (const char*)(g_WT_lo + go));
        }
        CP_COMMIT();
#pragma unroll
        for (int t = 0; t < 4; t++) {
            const int idx = tid + t * 256;
            const int row = idx >> 4;
            const int cg = (idx & 15) * 4;
            float4 v = *(const float4*)&h[(size_t)(m0 + row) * FF + k0 + cg];
            __half hx = __float2half_rn(v.x), hy = __float2half_rn(v.y);
            __half hz = __float2half_rn(v.z), hw = __float2half_rn(v.w);
            __half2 hA = __halves2half2(hx, hy), hB = __halves2half2(hz, hw);
            __half2 lA = __halves2half2(__float2half_rn(v.x - __half2float(hx)),
                                        __float2half_rn(v.y - __half2float(hy)));
            __half2 lB = __halves2half2(__float2half_rn(v.z - __half2float(hz)),
                                        __float2half_rn(v.w - __half2float(hw)));
            uint2 hv, lv;
            hv.x = *reinterpret_cast<uint32_t*>(&hA);
            hv.y = *reinterpret_cast<uint32_t*>(&hB);
            lv.x = *reinterpret_cast<uint32_t*>(&lA);
            lv.y = *reinterpret_cast<uint32_t*>(&lB);
            *(uint2*)(smem + GS_AH + row * VST + cg * 2) = hv;
            *(uint2*)(smem + GS_AL + row * VST + cg * 2) = lv;
        }
        CP_WAIT0();
        __syncthreads();

#pragma unroll
        for (int ks = 0; ks < 4; ks++) {
            const uint32_t kb = ks * 32;
            uint32_t ah[2][4], al[2][4];
            ldsm_x4(ah[0], a_off_h + kb);
            ldsm_x4(ah[1], a_off_h + 16 * VST + kb);
            ldsm_x4(al[0], a_off_l + kb);
            ldsm_x4(al[1], a_off_l + 16 * VST + kb);
#pragma unroll
            for (int ntp = 0; ntp < 4; ntp++) {
                const uint32_t bo = b_row + ntp * 16 * VST + kb;
                uint32_t bh[4], bl[4];
                ldsm_x4(bh, smem_base + GS_BH + bo);
                ldsm_x4(bl, smem_base + GS_BL + bo);
#pragma unroll
                for (int mt = 0; mt < 2; mt++) {
                    mma16816(acc[mt][ntp * 2 + 0], ah[mt], &bh[0]);
                    mma16816(acc[mt][ntp * 2 + 1], ah[mt], &bh[2]);
                    mma16816(acc[mt][ntp * 2 + 0], ah[mt], &bl[0]);
                    mma16816(acc[mt][ntp * 2 + 1], ah[mt], &bl[2]);
                    mma16816(acc[mt][ntp * 2 + 0], al[mt], &bh[0]);
                    mma16816(acc[mt][ntp * 2 + 1], al[mt], &bh[2]);
                }
            }
        }
        __syncthreads();
    }

    const int ldq = lane >> 2;
    float* st = (float*)smem;
    float* s1p = (float*)(smem + GS_S1P);
    float* s2p = (float*)(smem + GS_S2P);

    if (tid < 64) { s1p[tid] = 0.f; s2p[tid] = 0.f; }
#pragma unroll
    for (int mt = 0; mt < 2; mt++) {
        const int r0 = m0w + mt * 16 + ldq;
#pragma unroll
        for (int nt = 0; nt < 8; nt++) {
            const int c0 = n0w + nt * 8 + (lane & 3) * 2;
            st[(c0 + 0) * TSTR + r0] = acc[mt][nt][0];
            st[(c0 + 1) * TSTR + r0] = acc[mt][nt][1];
            st[(c0 + 0) * TSTR + r0 + 8] = acc[mt][nt][2];
            st[(c0 + 1) * TSTR + r0 + 8] = acc[mt][nt][3];
        }
    }
    __syncthreads();

#pragma unroll
    for (int mt = 0; mt < 2; mt++) {
        const int r0 = m0w + mt * 16 + ldq;
        float s1x = 0.f, s1y = 0.f, s2x = 0.f, s2y = 0.f;
#pragma unroll
        for (int nt = 0; nt < 8; nt++) {
            const int c0 = n0w + nt * 8 + (lane & 3) * 2;
            float a10 = aVec[c0], a11 = aVec[c0 + 1];
            float a20 = aVec[FF + c0], a21 = aVec[FF + c0 + 1];
            s1x += acc[mt][nt][0] * a10 + acc[mt][nt][1] * a11;
            s1y += acc[mt][nt][2] * a10 + acc[mt][nt][3] * a11;
            s2x += acc[mt][nt][0] * a20 + acc[mt][nt][1] * a21;
            s2y += acc[mt][nt][2] * a20 + acc[mt][nt][3] * a21;
        }
#pragma unroll
        for (int o = 1; o <= 2; o <<= 1) {
            s1x += __shfl_xor_sync(0xffffffffu, s1x, o);
            s1y += __shfl_xor_sync(0xffffffffu, s1y, o);
            s2x += __shfl_xor_sync(0xffffffffu, s2x, o);
            s2y += __shfl_xor_sync(0xffffffffu, s2y, o);
        }
        if ((lane & 3) == 0) {
            atomicAdd(&s1p[r0], s1x);
            atomicAdd(&s1p[r0 + 8], s1y);
            atomicAdd(&s2p[r0], s2x);
            atomicAdd(&s2p[r0 + 8], s2y);
        }
    }
    __syncthreads();

    __half* whtHiB = g_WhT_hi + (size_t)b * FF * NN + n_in_b;
    __half* whtLoB = g_WhT_lo + (size_t)b * FF * NN + n_in_b;
#pragma unroll
    for (int t = 0; t < 16; t++) {
        const int idx = tid + t * 256;
        const int f = idx >> 4;
        const int m4 = (idx & 15) * 4;
        float v0 = st[f * TSTR + m4 + 0];
        float v1 = st[f * TSTR + m4 + 1];
        float v2 = st[f * TSTR + m4 + 2];
        float v3 = st[f * TSTR + m4 + 3];
        __half h0 = __float2half_rn(v0), h1 = __float2half_rn(v1);
        __half h2 = __float2half_rn(v2), h3 = __float2half_rn(v3);
        __half2 hA = __halves2half2(h0, h1), hB = __halves2half2(h2, h3);
        __half2 lA = __halves2half2(__float2half_rn(v0 - __half2float(h0)),
                                    __float2half_rn(v1 - __half2float(h1)));
        __half2 lB = __halves2half2(__float2half_rn(v2 - __half2float(h2)),
                                    __float2half_rn(v3 - __half2float(h3)));
        uint2 hv, lv;
        hv.x = *reinterpret_cast<uint32_t*>(&hA);
        hv.y = *reinterpret_cast<uint32_t*>(&hB);
        lv.x = *reinterpret_cast<uint32_t*>(&lA);
        lv.y = *reinterpret_cast<uint32_t*>(&lB);
        *(uint2*)(whtHiB + (size_t)f * NN + m4) = hv;
        *(uint2*)(whtLoB + (size_t)f * NN + m4) = lv;
    }
    if (tid < 64) {
        g_s1[m0 + tid] = s1p[tid];
        g_s2[m0 + tid] = s2p[tid];
    }
}

// ============================================================
// Kernel 2: per-batch max of s2
// ============================================================
__global__ __launch_bounds__(256) void s2max_kernel()
{
    __shared__ float red[256];
    const int b = blockIdx.x;
    float m = -1e30f;
    for (int i = threadIdx.x; i < NN; i += 256) m = fmaxf(m, g_s2[b * NN + i]);
    red[threadIdx.x] = m;
    __syncthreads();
#pragma unroll
    for (int s = 128; s; s >>= 1) {
        if (threadIdx.x < s) red[threadIdx.x] = fmaxf(red[threadIdx.x], red[threadIdx.x + s]);
        __syncthreads();
    }
    if (threadIdx.x == 0) g_s2max[b] = red[0];
}

// ============================================================
// Kernel 3: fused masked softmax + PV, TI=128, double-buffered pipeline
// CTA: 128 queries x 256 features, 8 warps (4m x 2n), warp 32q x 128f
// ============================================================
#define TI 128
#define KJ 64
#define NJ (NN / KJ)

#define VBYT (FF * VST)                      // 36864 per operand per buffer
#define SM_VH0 0
#define SM_VL0 (SM_VH0 + VBYT)
#define SM_VH1 (SM_VL0 + VBYT)
#define SM_VL1 (SM_VH1 + VBYT)
#define SM_P0  (SM_VH1 + 2 * VBYT)           // 147456
#define SM_P1  (SM_P0 + TI * VST)            // 165888
#define SM_ZS  (SM_P1 + TI * VST)            // 184320
#define SM_TOTAL (SM_ZS + TI * 4)            // 184832

__global__ __launch_bounds__(256, 1) void attn_mma_kernel(
    const int* __restrict__ adj, float* __restrict__ out)
{
    extern __shared__ char smem[];
    const uint32_t smem_base = smem_u32(smem);
    const int tid = threadIdx.x;
    const int wid = tid >> 5;
    const int lane = tid & 31;
    const int b = blockIdx.y;
    const int i0 = blockIdx.x * TI;

    const int m0w = (wid & 3) * 32;      // 4 m-warps
    const int n0w = (wid >> 2) * 128;    // 2 n-warps

    // P-compute mapping: thread -> (row r, 32 j's at jhalf)
    const int r = tid >> 1;
    const int jhalf = (tid & 1) * 32;

    const float s1v = g_s1[b * NN + i0 + r];
    const float ms2 = g_s2max[b];
    const float tpre = s1v + ms2;
    const float mi = tpre > 0.f ? tpre : ALPHA * tpre;
    float zloc = 0.f;

    const int* __restrict__ adjR = adj + ((size_t)b * NN + i0 + r) * NN;
    const float* __restrict__ s2B = g_s2 + b * NN;
    const __half* __restrict__ whtHi = g_WhT_hi + (size_t)b * FF * NN;
    const __half* __restrict__ whtLo = g_WhT_lo + (size_t)b * FF * NN;

    float acc[2][16][4];
#pragma unroll
    for (int mt = 0; mt < 2; mt++)
#pragma unroll
        for (int nt = 0; nt < 16; nt++)
#pragma unroll
            for (int q = 0; q < 4; q++) acc[mt][nt][q] = 0.f;

    // ldmatrix per-lane offsets
    const uint32_t a_row = (uint32_t)(m0w + ((lane >> 3) & 1) * 8 + (lane & 7)) * VST
        + (uint32_t)(lane >> 4) * 16;
    const uint32_t b_row = (uint32_t)(n0w + ((lane >> 4) & 1) * 8 + (lane & 7)) * VST
        + (uint32_t)((lane >> 3) & 1) * 16;

    // V staging per-thread indices
    const int vf = tid >> 3;             // f-row base (stride 32 over it-loop via +32*...)
    const int vc = tid & 7;

    // ---- prologue: stage V0, compute P0 ----
    {
#pragma unroll
        for (int it = 0; it < 8; it++) {
            const int f = vf + it * 32;
            const uint32_t so = f * VST + vc * 16;
            const size_t go = (size_t)f * NN + 0 + vc * 8;
            CP_ASYNC16(smem_base + SM_VH0 + so, (const char*)(whtHi + go));
            CP_ASYNC16(smem_base + SM_VL0 + so, (const char*)(whtLo + go));
        }
        CP_COMMIT();
#pragma unroll
        for (int g = 0; g < 8; g++) {
            const int j = jhalf + g * 4;
            int4 am = *(const int4*)&adjR[j];
            float4 s2q = *(const float4*)&s2B[j];
            float p0, p1, p2, p3, ev;
            ev = s1v + s2q.x; ev = ev > 0.f ? ev : ALPHA * ev;
            p0 = (am.x > 0) ? __expf(ev - mi) : 0.f;
            ev = s1v + s2q.y; ev = ev > 0.f ? ev : ALPHA * ev;
            p1 = (am.y > 0) ? __expf(ev - mi) : 0.f;
            ev = s1v + s2q.z; ev = ev > 0.f ? ev : ALPHA * ev;
            p2 = (am.z > 0) ? __expf(ev - mi) : 0.f;
            ev = s1v + s2q.w; ev = ev > 0.f ? ev : ALPHA * ev;
            p3 = (am.w > 0) ? __expf(ev - mi) : 0.f;
            zloc += (p0 + p1) + (p2 + p3);
            __half2 hA = __floats2half2_rn(p0, p1);
            __half2 hB = __floats2half2_rn(p2, p3);
            uint2 hv;
            hv.x = *reinterpret_cast<uint32_t*>(&hA);
            hv.y = *reinterpret_cast<uint32_t*>(&hB);
            *(uint2*)(smem + SM_P0 + r * VST + (jhalf + g * 4) * 2) = hv;
        }
    }

    for (int jt = 0; jt < NJ; jt++) {
        const uint32_t vh = (jt & 1) ? SM_VH1 : SM_VH0;
        const uint32_t vl = (jt & 1) ? SM_VL1 : SM_VL0;
        const uint32_t pb = (jt & 1) ? SM_P1 : SM_P0;
        const uint32_t vhn = (jt & 1) ? SM_VH0 : SM_VH1;
        const uint32_t vln = (jt & 1) ? SM_VL0 : SM_VL1;
        const uint32_t pbn = (jt & 1) ? SM_P0 : SM_P1;
        const bool more = (jt + 1 < NJ);

        CP_WAIT0();
        __syncthreads();

        // issue next V tile + next adj loads (latency spans MMA phase)
        int4 am[8];
        if (more) {
            const int jn = (jt + 1) * KJ;
#pragma unroll
            for (int it = 0; it < 8; it++) {
                const int f = vf + it * 32;
                const uint32_t so = f * VST + vc * 16;
                const size_t go = (size_t)f * NN + jn + vc * 8;
                CP_ASYNC16(smem_base + vhn + so, (const char*)(whtHi + go));
                CP_ASYNC16(smem_base + vln + so, (const char*)(whtLo + go));
            }
            CP_COMMIT();
#pragma unroll
            for (int g = 0; g < 8; g++)
                am[g] = *(const int4*)&adjR[jn + jhalf + g * 4];
        }

        // ---- HMMA on current buffers ----
#pragma unroll
        for (int ks = 0; ks < 4; ks++) {
            const uint32_t kb = ks * 32;
            uint32_t ah[2][4];
            ldsm_x4(ah[0], smem_base + pb + a_row + kb);
            ldsm_x4(ah[1], smem_base + pb + a_row + 16 * VST + kb);
#pragma unroll
            for (int ntp = 0; ntp < 8; ntp++) {
                const uint32_t bo = b_row + ntp * 16 * VST + kb;
                uint32_t bh[4], bl[4];
                ldsm_x4(bh, smem_base + vh + bo);
                ldsm_x4(bl, smem_base + vl + bo);
#pragma unroll
                for (int mt = 0; mt < 2; mt++) {
                    mma16816(acc[mt][ntp * 2 + 0], ah[mt], &bh[0]);
                    mma16816(acc[mt][ntp * 2 + 1], ah[mt], &bh[2]);
                    mma16816(acc[mt][ntp * 2 + 0], ah[mt], &bl[0]);
                    mma16816(acc[mt][ntp * 2 + 1], ah[mt], &bl[2]);
                }
            }
        }

        // ---- compute next P tile into other buffer ----
        if (more) {
            const int jn = (jt + 1) * KJ;
#pragma unroll
            for (int g = 0; g < 8; g++) {
                const int j = jn + jhalf + g * 4;
                float4 s2q = *(const float4*)&s2B[j];
                float p0, p1, p2, p3, ev;
                ev = s1v + s2q.x; ev = ev > 0.f ? ev : ALPHA * ev;
                p0 = (am[g].x > 0) ? __expf(ev - mi) : 0.f;
                ev = s1v + s2q.y; ev = ev > 0.f ? ev : ALPHA * ev;
                p1 = (am[g].y > 0) ? __expf(ev - mi) : 0.f;
                ev = s1v + s2q.z; ev = ev > 0.f ? ev : ALPHA * ev;
                p2 = (am[g].z > 0) ? __expf(ev - mi) : 0.f;
                ev = s1v + s2q.w; ev = ev > 0.f ? ev : ALPHA * ev;
                p3 = (am[g].w > 0) ? __expf(ev - mi) : 0.f;
                zloc += (p0 + p1) + (p2 + p3);
                __half2 hA = __floats2half2_rn(p0, p1);
                __half2 hB = __floats2half2_rn(p2, p3);
                uint2 hv;
                hv.x = *reinterpret_cast<uint32_t*>(&hA);
                hv.y = *reinterpret_cast<uint32_t*>(&hB);
                *(uint2*)(smem + pbn + r * VST + (jhalf + g * 4) * 2) = hv;
            }
        }
    }

    // ---- Z reduction (thread pairs share a row) ----
    zloc += __shfl_xor_sync(0xffffffffu, zloc, 1);
    if ((tid & 1) == 0) *(float*)(smem + SM_ZS + r * 4) = zloc;
    __syncthreads();

    // ---- epilogue: out = acc / Z ----
    const float* Zs = (const float*)(smem + SM_ZS);
    const int ldq = lane >> 2;
#pragma unroll
    for (int mt = 0; mt < 2; mt++) {
        const int row0 = m0w + mt * 16 + ldq;
        const float rz0 = 1.f / Zs[row0];
        const float rz1 = 1.f / Zs[row0 + 8];
        float* __restrict__ o0 = out + ((size_t)b * NN + i0 + row0) * FF;
        float* __restrict__ o1 = o0 + 8 * FF;
#pragma unroll
        for (int nt = 0; nt < 16; nt++) {
            const int col = n0w + nt * 8 + (lane & 3) * 2;
            float2 v0 = make_float2(acc[mt][nt][0] * rz0, acc[mt][nt][1] * rz0);
            float2 v1 = make_float2(acc[mt][nt][2] * rz1, acc[mt][nt][3] * rz1);
            *(float2*)&o0[col] = v0;
            *(float2*)&o1[col] = v1;
        }
    }
}

// ============================================================
// launch
// ============================================================
extern "C" void kernel_launch(void* const* d_in, const int* in_sizes, int n_in,
                              void* d_out, int out_size)
{
    const float* h   = (const float*)d_in[0];
    const int*   adj = (const int*)d_in[1];
    const float* W   = (const float*)d_in[2];
    const float* a   = (const float*)d_in[3];
    float* out = (float*)d_out;

    cudaFuncSetAttribute(gemm_fused_kernel,
                         cudaFuncAttributeMaxDynamicSharedMemorySize, GS_TOTAL);
    cudaFuncSetAttribute(attn_mma_kernel,
                         cudaFuncAttributeMaxDynamicSharedMemorySize, SM_TOTAL);

    dim3 g0(FF / 32, FF / 32);
    prep_wt_kernel<<<g0, 256>>>(W);

    gemm_fused_kernel<<<BB * NN / 64, 256, GS_TOTAL>>>(h, a);

    s2max_kernel<<<BB, 256>>>();

    dim3 g4(NN / TI, BB);
    attn_mma_kernel<<<g4, 256, SM_TOTAL>>>(adj, out);
}

// round 8
// speedup vs baseline: 1.0202x; 1.0202x over previous
#include <cuda_runtime.h>
#include <cuda_fp16.h>
#include <cstdint>

#define BB 8
#define NN 2048
#define FF 256
#define ALPHA 0.2f

// -------- scratch (device globals; no allocation allowed) --------
__device__ __half g_WhT_hi[BB * FF * NN];     // 8 MB  (Wh^T, fp16 high part)
__device__ __half g_WhT_lo[BB * FF * NN];     // 8 MB  (Wh^T, fp16 low part)
__device__ __half g_WT_hi[FF * FF];           // W^T fp16 hi  [f][k]
__device__ __half g_WT_lo[FF * FF];           // W^T fp16 lo
__device__ float g_s1[BB * NN];
__device__ float g_s2[BB * NN];
__device__ float g_s2max[BB];

// ============================================================
// common helpers
// ============================================================
__device__ __forceinline__ void mma16816(float* c, const uint32_t* a, const uint32_t* b)
{
    asm volatile(
        "mma.sync.aligned.m16n8k16.row.col.f32.f16.f16.f32 "
        "{%0,%1,%2,%3}, {%4,%5,%6,%7}, {%8,%9}, {%0,%1,%2,%3};"
        : "+f"(c[0]), "+f"(c[1]), "+f"(c[2]), "+f"(c[3])
        : "r"(a[0]), "r"(a[1]), "r"(a[2]), "r"(a[3]), "r"(b[0]), "r"(b[1]));
}
__device__ __forceinline__ void ldsm_x4(uint32_t* r, uint32_t addr)
{
    asm volatile("ldmatrix.sync.aligned.m8n8.x4.shared.b16 {%0,%1,%2,%3}, [%4];"
        : "=r"(r[0]), "=r"(r[1]), "=r"(r[2]), "=r"(r[3]) : "r"(addr));
}
__device__ __forceinline__ uint32_t smem_u32(const void* p) {
    uint32_t a;
    asm("{ .reg .u64 t; cvta.to.shared.u64 t, %1; cvt.u32.u64 %0, t; }" : "=r"(a) : "l"(p));
    return a;
}
#define CP_ASYNC16(dst, src) asm volatile("cp.async.cg.shared.global [%0], [%1], 16;" :: "r"(dst), "l"(src) : "memory")
#define CP_COMMIT()  asm volatile("cp.async.commit_group;" ::: "memory")
#define CP_WAIT0()   asm volatile("cp.async.wait_group 0;" ::: "memory")
#define CP_WAIT1()   asm volatile("cp.async.wait_group 1;" ::: "memory")

#define VST 144   // gemm kernel row stride (64 fp16 + pad)

// ============================================================
// Kernel 0: W [k][f] fp32 -> W^T hi/lo fp16 [f][k]
// ============================================================
__global__ __launch_bounds__(256) void prep_wt_kernel(const float* __restrict__ W)
{
    __shared__ float t[32][33];
    const int k0 = blockIdx.x * 32, f0 = blockIdx.y * 32;
    const int x = threadIdx.x & 31, y = threadIdx.x >> 5;
#pragma unroll
    for (int r = 0; r < 4; r++)
        t[y * 4 + r][x] = W[(size_t)(k0 + y * 4 + r) * FF + f0 + x];
    __syncthreads();
#pragma unroll
    for (int r = 0; r < 4; r++) {
        const int f = f0 + y * 4 + r;
        float v = t[x][y * 4 + r];
        __half hi = __float2half_rn(v);
        g_WT_hi[(size_t)f * FF + k0 + x] = hi;
        g_WT_lo[(size_t)f * FF + k0 + x] = __float2half_rn(v - __half2float(hi));
    }
}

// ============================================================
// Kernel 1: fused Wh GEMM (split-fp16 3-pass mma) + s1/s2 + WhT hi/lo
// (unchanged from R6)
// ============================================================
#define GS_BH 0
#define GS_BL (GS_BH + FF * VST)
#define GS_AH (GS_BL + FF * VST)
#define GS_AL (GS_AH + 64 * VST)
#define GS_S1P (GS_AL + 64 * VST)
#define GS_S2P (GS_S1P + 64 * 4)
#define GS_TOTAL (GS_S2P + 64 * 4)
#define TSTR 66

__global__ __launch_bounds__(256, 2) void gemm_fused_kernel(
    const float* __restrict__ h, const float* __restrict__ aVec)
{
    extern __shared__ char smem[];
    const uint32_t smem_base = smem_u32(smem);
    const int tid = threadIdx.x;
    const int wid = tid >> 5;
    const int lane = tid & 31;
    const int m0 = blockIdx.x * 64;
    const int b = m0 / NN;
    const int n_in_b = m0 - b * NN;

    const int m0w = (wid & 1) * 32;
    const int n0w = (wid >> 1) * 64;

    float acc[2][8][4];
#pragma unroll
    for (int mt = 0; mt < 2; mt++)
#pragma unroll
        for (int nt = 0; nt < 8; nt++)
#pragma unroll
            for (int q = 0; q < 4; q++) acc[mt][nt][q] = 0.f;

    const uint32_t a_off_h = smem_base + GS_AH
        + (uint32_t)(m0w + ((lane >> 3) & 1) * 8 + (lane & 7)) * VST
        + (uint32_t)(lane >> 4) * 16;
    const uint32_t a_off_l = a_off_h + (GS_AL - GS_AH);
    const uint32_t b_row = (uint32_t)(n0w + ((lane >> 4) & 1) * 8 + (lane & 7)) * VST
        + (uint32_t)((lane >> 3) & 1) * 16;

    for (int kt = 0; kt < 4; kt++) {
        const int k0 = kt * 64;
#pragma unroll
        for (int it = 0; it < 8; it++) {
            const int idx = tid + it * 256;
            const int f = idx >> 3;
            const int c = idx & 7;
            const uint32_t so = f * VST + c * 16;
            const size_t go = (size_t)f * FF + k0 + c * 8;
            CP_ASYNC16(smem_base + GS_BH + so, (const char*)(g_WT_hi + go));
            CP_ASYNC16(smem_base + GS_BL + so, (const char*)(g_WT_lo + go));
        }
        CP_COMMIT();
#pragma unroll
        for (int t = 0; t < 4; t++) {
            const int idx = tid + t * 256;
            const int row = idx >> 4;
            const int cg = (idx & 15) * 4;
            float4 v = *(const float4*)&h[(size_t)(m0 + row) * FF + k0 + cg];
            __half hx = __float2half_rn(v.x), hy = __float2half_rn(v.y);
            __half hz = __float2half_rn(v.z), hw = __float2half_rn(v.w);
            __half2 hA = __halves2half2(hx, hy), hB = __halves2half2(hz, hw);
            __half2 lA = __halves2half2(__float2half_rn(v.x - __half2float(hx)),
                                        __float2half_rn(v.y - __half2float(hy)));
            __half2 lB = __halves2half2(__float2half_rn(v.z - __half2float(hz)),
                                        __float2half_rn(v.w - __half2float(hw)));
            uint2 hv, lv;
            hv.x = *reinterpret_cast<uint32_t*>(&hA);
            hv.y = *reinterpret_cast<uint32_t*>(&hB);
            lv.x = *reinterpret_cast<uint32_t*>(&lA);
            lv.y = *reinterpret_cast<uint32_t*>(&lB);
            *(uint2*)(smem + GS_AH + row * VST + cg * 2) = hv;
            *(uint2*)(smem + GS_AL + row * VST + cg * 2) = lv;
        }
        CP_WAIT0();
        __syncthreads();

#pragma unroll
        for (int ks = 0; ks < 4; ks++) {
            const uint32_t kb = ks * 32;
            uint32_t ah[2][4], al[2][4];
            ldsm_x4(ah[0], a_off_h + kb);
            ldsm_x4(ah[1], a_off_h + 16 * VST + kb);
            ldsm_x4(al[0], a_off_l + kb);
            ldsm_x4(al[1], a_off_l + 16 * VST + kb);
#pragma unroll
            for (int ntp = 0; ntp < 4; ntp++) {
                const uint32_t bo = b_row + ntp * 16 * VST + kb;
                uint32_t bh[4], bl[4];
                ldsm_x4(bh, smem_base + GS_BH + bo);
                ldsm_x4(bl, smem_base + GS_BL + bo);
#pragma unroll
                for (int mt = 0; mt < 2; mt++) {
                    mma16816(acc[mt][ntp * 2 + 0], ah[mt], &bh[0]);
                    mma16816(acc[mt][ntp * 2 + 1], ah[mt], &bh[2]);
                    mma16816(acc[mt][ntp * 2 + 0], ah[mt], &bl[0]);
                    mma16816(acc[mt][ntp * 2 + 1], ah[mt], &bl[2]);
                    mma16816(acc[mt][ntp * 2 + 0], al[mt], &bh[0]);
                    mma16816(acc[mt][ntp * 2 + 1], al[mt], &bh[2]);
                }
            }
        }
        __syncthreads();
    }

    const int ldq = lane >> 2;
    float* st = (float*)smem;
    float* s1p = (float*)(smem + GS_S1P);
    float* s2p = (float*)(smem + GS_S2P);

    if (tid < 64) { s1p[tid] = 0.f; s2p[tid] = 0.f; }
#pragma unroll
    for (int mt = 0; mt < 2; mt++) {
        const int r0 = m0w + mt * 16 + ldq;
#pragma unroll
        for (int nt = 0; nt < 8; nt++) {
            const int c0 = n0w + nt * 8 + (lane & 3) * 2;
            st[(c0 + 0) * TSTR + r0] = acc[mt][nt][0];
            st[(c0 + 1) * TSTR + r0] = acc[mt][nt][1];
            st[(c0 + 0) * TSTR + r0 + 8] = acc[mt][nt][2];
            st[(c0 + 1) * TSTR + r0 + 8] = acc[mt][nt][3];
        }
    }
    __syncthreads();

#pragma unroll
    for (int mt = 0; mt < 2; mt++) {
        const int r0 = m0w + mt * 16 + ldq;
        float s1x = 0.f, s1y = 0.f, s2x = 0.f, s2y = 0.f;
#pragma unroll
        for (int nt = 0; nt < 8; nt++) {
            const int c0 = n0w + nt * 8 + (lane & 3) * 2;
            float a10 = aVec[c0], a11 = aVec[c0 + 1];
            float a20 = aVec[FF + c0], a21 = aVec[FF + c0 + 1];
            s1x += acc[mt][nt][0] * a10 + acc[mt][nt][1] * a11;
            s1y += acc[mt][nt][2] * a10 + acc[mt][nt][3] * a11;
            s2x += acc[mt][nt][0] * a20 + acc[mt][nt][1] * a21;
            s2y += acc[mt][nt][2] * a20 + acc[mt][nt][3] * a21;
        }
#pragma unroll
        for (int o = 1; o <= 2; o <<= 1) {
            s1x += __shfl_xor_sync(0xffffffffu, s1x, o);
            s1y += __shfl_xor_sync(0xffffffffu, s1y, o);
            s2x += __shfl_xor_sync(0xffffffffu, s2x, o);
            s2y += __shfl_xor_sync(0xffffffffu, s2y, o);
        }
        if ((lane & 3) == 0) {
            atomicAdd(&s1p[r0], s1x);
            atomicAdd(&s1p[r0 + 8], s1y);
            atomicAdd(&s2p[r0], s2x);
            atomicAdd(&s2p[r0 + 8], s2y);
        }
    }
    __syncthreads();

    __half* whtHiB = g_WhT_hi + (size_t)b * FF * NN + n_in_b;
    __half* whtLoB = g_WhT_lo + (size_t)b * FF * NN + n_in_b;
#pragma unroll
    for (int t = 0; t < 16; t++) {
        const int idx = tid + t * 256;
        const int f = idx >> 4;
        const int m4 = (idx & 15) * 4;
        float v0 = st[f * TSTR + m4 + 0];
        float v1 = st[f * TSTR + m4 + 1];
        float v2 = st[f * TSTR + m4 + 2];
        float v3 = st[f * TSTR + m4 + 3];
        __half h0 = __float2half_rn(v0), h1 = __float2half_rn(v1);
        __half h2 = __float2half_rn(v2), h3 = __float2half_rn(v3);
        __half2 hA = __halves2half2(h0, h1), hB = __halves2half2(h2, h3);
        __half2 lA = __halves2half2(__float2half_rn(v0 - __half2float(h0)),
                                    __float2half_rn(v1 - __half2float(h1)));
        __half2 lB = __halves2half2(__float2half_rn(v2 - __half2float(h2)),
                                    __float2half_rn(v3 - __half2float(h3)));
        uint2 hv, lv;
        hv.x = *reinterpret_cast<uint32_t*>(&hA);
        hv.y = *reinterpret_cast<uint32_t*>(&hB);
        lv.x = *reinterpret_cast<uint32_t*>(&lA);
        lv.y = *reinterpret_cast<uint32_t*>(&lB);
        *(uint2*)(whtHiB + (size_t)f * NN + m4) = hv;
        *(uint2*)(whtLoB + (size_t)f * NN + m4) = lv;
    }
    if (tid < 64) {
        g_s1[m0 + tid] = s1p[tid];
        g_s2[m0 + tid] = s2p[tid];
    }
}

// ============================================================
// Kernel 2: per-batch max of s2
// ============================================================
__global__ __launch_bounds__(256) void s2max_kernel()
{
    __shared__ float red[256];
    const int b = blockIdx.x;
    float m = -1e30f;
    for (int i = threadIdx.x; i < NN; i += 256) m = fmaxf(m, g_s2[b * NN + i]);
    red[threadIdx.x] = m;
    __syncthreads();
#pragma unroll
    for (int s = 128; s; s >>= 1) {
        if (threadIdx.x < s) red[threadIdx.x] = fmaxf(red[threadIdx.x], red[threadIdx.x + s]);
        __syncthreads();
    }
    if (threadIdx.x == 0) g_s2max[b] = red[0];
}

// ============================================================
// Kernel 3: fused masked softmax + PV, TI=64, KJ=32,
// double-buffered V & P, one barrier per tile, 2 CTAs/SM
// ============================================================
#define TI 64
#define KJ 32
#define NJ (NN / KJ)
#define AST 80                               // 32 fp16 (64B) + 16B pad

#define VOPB (FF * AST)                      // 20480 per operand per buffer
#define SM_VH0 0
#define SM_VL0 (SM_VH0 + VOPB)
#define SM_VH1 (SM_VL0 + VOPB)
#define SM_VL1 (SM_VH1 + VOPB)
#define SM_P0  (SM_VH1 + 2 * VOPB)           // 81920
#define SM_P1  (SM_P0 + TI * AST)            // 87040
#define SM_ZS  (SM_P1 + TI * AST)            // 92160
#define SM_TOTAL (SM_ZS + TI * 4)            // 92416

__global__ __launch_bounds__(256, 2) void attn_mma_kernel(
    const int* __restrict__ adj, float* __restrict__ out)
{
    extern __shared__ char smem[];
    const uint32_t smem_base = smem_u32(smem);
    const int tid = threadIdx.x;
    const int wid = tid >> 5;
    const int lane = tid & 31;
    const int b = blockIdx.y;
    const int i0 = blockIdx.x * TI;

    const int m0w = (wid & 1) * 32;
    const int n0w = (wid >> 1) * 64;

    // P-compute mapping: thread -> (row r, 8 j's at jq)
    const int r = tid >> 2;
    const int jq = (tid & 3) * 8;

    const float s1v = g_s1[b * NN + i0 + r];
    const float ms2 = g_s2max[b];
    const float tpre = s1v + ms2;
    const float mi = tpre > 0.f ? tpre : ALPHA * tpre;
    float zloc = 0.f;

    const int* __restrict__ adjR = adj + ((size_t)b * NN + i0 + r) * NN;
    const float* __restrict__ s2B = g_s2 + b * NN;
    const __half* __restrict__ whtHi = g_WhT_hi + (size_t)b * FF * NN;
    const __half* __restrict__ whtLo = g_WhT_lo + (size_t)b * FF * NN;

    float acc[2][8][4];
#pragma unroll
    for (int mt = 0; mt < 2; mt++)
#pragma unroll
        for (int nt = 0; nt < 8; nt++)
#pragma unroll
            for (int q = 0; q < 4; q++) acc[mt][nt][q] = 0.f;

    // ldmatrix per-lane offsets
    const uint32_t a_row = (uint32_t)(m0w + ((lane >> 3) & 1) * 8 + (lane & 7)) * AST
        + (uint32_t)(lane >> 4) * 16;
    const uint32_t b_row = (uint32_t)(n0w + ((lane >> 4) & 1) * 8 + (lane & 7)) * AST
        + (uint32_t)((lane >> 3) & 1) * 16;

    // V staging: per op per buffer = 256 rows x 64B = 1024 x 16B chunks -> 4/thread
    const int vf = tid >> 2;          // base f-row (stride 64 over it)
    const int vc = tid & 3;

    // P compute helper macro body (computes 8 j's from am0/am1 into buffer pb)
#define P_COMPUTE(JTILE, AM0, AM1, PB)                                          \
    {                                                                            \
        const int jj = (JTILE) * KJ + jq;                                        \
        float4 s2a = *(const float4*)&s2B[jj];                                   \
        float4 s2b = *(const float4*)&s2B[jj + 4];                               \
        float p0, p1, p2, p3, p4, p5, p6, p7, ev;                                \
        ev = s1v + s2a.x; ev = ev > 0.f ? ev : ALPHA * ev;                       \
        p0 = ((AM0).x > 0) ? __expf(ev - mi) : 0.f;                              \
        ev = s1v + s2a.y; ev = ev > 0.f ? ev : ALPHA * ev;                       \
        p1 = ((AM0).y > 0) ? __expf(ev - mi) : 0.f;                              \
        ev = s1v + s2a.z; ev = ev > 0.f ? ev : ALPHA * ev;                       \
        p2 = ((AM0).z > 0) ? __expf(ev - mi) : 0.f;                              \
        ev = s1v + s2a.w; ev = ev > 0.f ? ev : ALPHA * ev;                       \
        p3 = ((AM0).w > 0) ? __expf(ev - mi) : 0.f;                              \
        ev = s1v + s2b.x; ev = ev > 0.f ? ev : ALPHA * ev;                       \
        p4 = ((AM1).x > 0) ? __expf(ev - mi) : 0.f;                              \
        ev = s1v + s2b.y; ev = ev > 0.f ? ev : ALPHA * ev;                       \
        p5 = ((AM1).y > 0) ? __expf(ev - mi) : 0.f;                              \
        ev = s1v + s2b.z; ev = ev > 0.f ? ev : ALPHA * ev;                       \
        p6 = ((AM1).z > 0) ? __expf(ev - mi) : 0.f;                              \
        ev = s1v + s2b.w; ev = ev > 0.f ? ev : ALPHA * ev;                       \
        p7 = ((AM1).w > 0) ? __expf(ev - mi) : 0.f;                              \
        zloc += ((p0 + p1) + (p2 + p3)) + ((p4 + p5) + (p6 + p7));               \
        __half2 q0 = __floats2half2_rn(p0, p1);                                  \
        __half2 q1 = __floats2half2_rn(p2, p3);                                  \
        __half2 q2 = __floats2half2_rn(p4, p5);                                  \
        __half2 q3 = __floats2half2_rn(p6, p7);                                  \
        uint4 pv;                                                                \
        pv.x = *reinterpret_cast<uint32_t*>(&q0);                                \
        pv.y = *reinterpret_cast<uint32_t*>(&q1);                                \
        pv.z = *reinterpret_cast<uint32_t*>(&q2);                                \
        pv.w = *reinterpret_cast<uint32_t*>(&q3);                                \
        *(uint4*)(smem + (PB) + r * AST + jq * 2) = pv;                          \
    }

#define V_ISSUE(JTILE, VH, VL)                                                  \
    {                                                                            \
        const int jn = (JTILE) * KJ;                                             \
        _Pragma("unroll")                                                        \
        for (int it = 0; it < 4; it++) {                                         \
            const int f = vf + it * 64;                                          \
            const uint32_t so = f * AST + vc * 16;                               \
            const size_t go = (size_t)f * NN + jn + vc * 8;                      \
            CP_ASYNC16(smem_base + (VH) + so, (const char*)(whtHi + go));        \
            CP_ASYNC16(smem_base + (VL) + so, (const char*)(whtLo + go));        \
        }                                                                        \
        CP_COMMIT();                                                             \
    }

    // ---- prologue ----
    int4 am0 = *(const int4*)&adjR[jq];
    int4 am1 = *(const int4*)&adjR[jq + 4];
    V_ISSUE(0, SM_VH0, SM_VL0);
    P_COMPUTE(0, am0, am1, SM_P0);
    V_ISSUE(1, SM_VH1, SM_VL1);
    am0 = *(const int4*)&adjR[KJ + jq];
    am1 = *(const int4*)&adjR[KJ + jq + 4];
    CP_WAIT1();            // V[0] complete (V[1] may be pending)
    __syncthreads();

    for (int jt = 0; jt < NJ; jt++) {
        const uint32_t vh = (jt & 1) ? SM_VH1 : SM_VH0;
        const uint32_t vl = (jt & 1) ? SM_VL1 : SM_VL0;
        const uint32_t pb = (jt & 1) ? SM_P1 : SM_P0;
        const uint32_t pbn = (jt & 1) ? SM_P0 : SM_P1;

        // ---- HMMA on current buffers ----
#pragma unroll
        for (int ks = 0; ks < 2; ks++) {
            const uint32_t kb = ks * 32;
            uint32_t ah[2][4];
            ldsm_x4(ah[0], smem_base + pb + a_row + kb);
            ldsm_x4(ah[1], smem_base + pb + a_row + 16 * AST + kb);
#pragma unroll
            for (int ntp = 0; ntp < 4; ntp++) {
                const uint32_t bo = b_row + ntp * 16 * AST + kb;
                uint32_t bh[4], bl[4];
                ldsm_x4(bh, smem_base + vh + bo);
                ldsm_x4(bl, smem_base + vl + bo);
#pragma unroll
                for (int mt = 0; mt < 2; mt++) {
                    mma16816(acc[mt][ntp * 2 + 0], ah[mt], &bh[0]);
                    mma16816(acc[mt][ntp * 2 + 1], ah[mt], &bh[2]);
                    mma16816(acc[mt][ntp * 2 + 0], ah[mt], &bl[0]);
                    mma16816(acc[mt][ntp * 2 + 1], ah[mt], &bl[2]);
                }
            }
        }

        // ---- compute P[t+1] into other buffer (MMA of t doesn't touch it) ----
        if (jt + 1 < NJ)
            P_COMPUTE(jt + 1, am0, am1, pbn);

        // ---- prefetch adj[t+2] (latency spans next iteration) ----
        if (jt + 2 < NJ) {
            const int jn2 = (jt + 2) * KJ;
            am0 = *(const int4*)&adjR[jn2 + jq];
            am1 = *(const int4*)&adjR[jn2 + jq + 4];
        }

        // ---- wait V[t+1], fence, issue V[t+2] into V[t]'s buffer ----
        CP_WAIT0();
        __syncthreads();
        if (jt + 2 < NJ)
            V_ISSUE(jt + 2, vh, vl);
    }

    // ---- Z reduction (quads share a row) ----
    zloc += __shfl_xor_sync(0xffffffffu, zloc, 1);
    zloc += __shfl_xor_sync(0xffffffffu, zloc, 2);
    if ((tid & 3) == 0) *(float*)(smem + SM_ZS + r * 4) = zloc;
    __syncthreads();

    // ---- epilogue: out = acc / Z ----
    const float* Zs = (const float*)(smem + SM_ZS);
    const int ldq = lane >> 2;
#pragma unroll
    for (int mt = 0; mt < 2; mt++) {
        const int row0 = m0w + mt * 16 + ldq;
        const float rz0 = 1.f / Zs[row0];
        const float rz1 = 1.f / Zs[row0 + 8];
        float* __restrict__ o0 = out + ((size_t)b * NN + i0 + row0) * FF;
        float* __restrict__ o1 = o0 + 8 * FF;
#pragma unroll
        for (int nt = 0; nt < 8; nt++) {
            const int col = n0w + nt * 8 + (lane & 3) * 2;
            float2 v0 = make_float2(acc[mt][nt][0] * rz0, acc[mt][nt][1] * rz0);
            float2 v1 = make_float2(acc[mt][nt][2] * rz1, acc[mt][nt][3] * rz1);
            *(float2*)&o0[col] = v0;
            *(float2*)&o1[col] = v1;
        }
    }
}

// ============================================================
// launch
// ============================================================
extern "C" void kernel_launch(void* const* d_in, const int* in_sizes, int n_in,
                              void* d_out, int out_size)
{
    const float* h   = (const float*)d_in[0];
    const int*   adj = (const int*)d_in[1];
    const float* W   = (const float*)d_in[2];
    const float* a   = (const float*)d_in[3];
    float* out = (float*)d_out;

    cudaFuncSetAttribute(gemm_fused_kernel,
                         cudaFuncAttributeMaxDynamicSharedMemorySize, GS_TOTAL);
    cudaFuncSetAttribute(attn_mma_kernel,
                         cudaFuncAttributeMaxDynamicSharedMemorySize, SM_TOTAL);

    dim3 g0(FF / 32, FF / 32);
    prep_wt_kernel<<<g0, 256>>>(W);

    gemm_fused_kernel<<<BB * NN / 64, 256, GS_TOTAL>>>(h, a);

    s2max_kernel<<<BB, 256>>>();

    dim3 g4(NN / TI, BB);
    attn_mma_kernel<<<g4, 256, SM_TOTAL>>>(adj, out);
}

// round 9
// speedup vs baseline: 1.6190x; 1.5871x over previous
#include <cuda_runtime.h>
#include <cuda_fp16.h>
#include <cstdint>

#define BB 8
#define NN 2048
#define FF 256
#define ALPHA 0.2f

// -------- scratch (device globals; no allocation allowed) --------
__device__ __half g_WhT[BB * FF * NN];        // 8 MB  (Wh^T, fp16)
__device__ __half g_WT_hi[FF * FF];           // W^T fp16 hi  [f][k]
__device__ __half g_WT_lo[FF * FF];           // W^T fp16 lo
__device__ float g_s1[BB * NN];
__device__ float g_s2[BB * NN];
__device__ float g_s2max[BB];

// ============================================================
// common helpers
// ============================================================
__device__ __forceinline__ void mma16816(float* c, const uint32_t* a, const uint32_t* b)
{
    asm volatile(
        "mma.sync.aligned.m16n8k16.row.col.f32.f16.f16.f32 "
        "{%0,%1,%2,%3}, {%4,%5,%6,%7}, {%8,%9}, {%0,%1,%2,%3};"
        : "+f"(c[0]), "+f"(c[1]), "+f"(c[2]), "+f"(c[3])
        : "r"(a[0]), "r"(a[1]), "r"(a[2]), "r"(a[3]), "r"(b[0]), "r"(b[1]));
}
__device__ __forceinline__ void ldsm_x4(uint32_t* r, uint32_t addr)
{
    asm volatile("ldmatrix.sync.aligned.m8n8.x4.shared.b16 {%0,%1,%2,%3}, [%4];"
        : "=r"(r[0]), "=r"(r[1]), "=r"(r[2]), "=r"(r[3]) : "r"(addr));
}
__device__ __forceinline__ uint32_t smem_u32(const void* p) {
    uint32_t a;
    asm("{ .reg .u64 t; cvta.to.shared.u64 t, %1; cvt.u32.u64 %0, t; }" : "=r"(a) : "l"(p));
    return a;
}
#define CP_ASYNC16(dst, src) asm volatile("cp.async.cg.shared.global [%0], [%1], 16;" :: "r"(dst), "l"(src) : "memory")
#define CP_COMMIT()  asm volatile("cp.async.commit_group;" ::: "memory")
#define CP_WAIT0()   asm volatile("cp.async.wait_group 0;" ::: "memory")

#define VST 144   // smem row stride (64 fp16 + pad) -> conflict-free LDSM

// ============================================================
// Kernel 0: W [k][f] fp32 -> W^T hi/lo fp16 [f][k]
// ============================================================
__global__ __launch_bounds__(256) void prep_wt_kernel(const float* __restrict__ W)
{
    __shared__ float t[32][33];
    const int k0 = blockIdx.x * 32, f0 = blockIdx.y * 32;
    const int x = threadIdx.x & 31, y = threadIdx.x >> 5;
#pragma unroll
    for (int r = 0; r < 4; r++)
        t[y * 4 + r][x] = W[(size_t)(k0 + y * 4 + r) * FF + f0 + x];
    __syncthreads();
#pragma unroll
    for (int r = 0; r < 4; r++) {
        const int f = f0 + y * 4 + r;
        float v = t[x][y * 4 + r];
        __half hi = __float2half_rn(v);
        g_WT_hi[(size_t)f * FF + k0 + x] = hi;
        g_WT_lo[(size_t)f * FF + k0 + x] = __float2half_rn(v - __half2float(hi));
    }
}

// ============================================================
// Kernel 1: fused Wh GEMM (split-fp16 3-pass mma) + s1/s2 + WhT fp16
// CTA: 64 nodes x 256 features, 8 warps (2m x 4n)
// ============================================================
#define GS_BH 0
#define GS_BL (GS_BH + FF * VST)
#define GS_AH (GS_BL + FF * VST)
#define GS_AL (GS_AH + 64 * VST)
#define GS_S1P (GS_AL + 64 * VST)
#define GS_S2P (GS_S1P + 64 * 4)
#define GS_TOTAL (GS_S2P + 64 * 4)
#define TSTR 66

__global__ __launch_bounds__(256, 2) void gemm_fused_kernel(
    const float* __restrict__ h, const float* __restrict__ aVec)
{
    extern __shared__ char smem[];
    const uint32_t smem_base = smem_u32(smem);
    const int tid = threadIdx.x;
    const int wid = tid >> 5;
    const int lane = tid & 31;
    const int m0 = blockIdx.x * 64;
    const int b = m0 / NN;
    const int n_in_b = m0 - b * NN;

    const int m0w = (wid & 1) * 32;
    const int n0w = (wid >> 1) * 64;

    float acc[2][8][4];
#pragma unroll
    for (int mt = 0; mt < 2; mt++)
#pragma unroll
        for (int nt = 0; nt < 8; nt++)
#pragma unroll
            for (int q = 0; q < 4; q++) acc[mt][nt][q] = 0.f;

    const uint32_t a_off_h = smem_base + GS_AH
        + (uint32_t)(m0w + ((lane >> 3) & 1) * 8 + (lane & 7)) * VST
        + (uint32_t)(lane >> 4) * 16;
    const uint32_t a_off_l = a_off_h + (GS_AL - GS_AH);
    const uint32_t b_row = (uint32_t)(n0w + ((lane >> 4) & 1) * 8 + (lane & 7)) * VST
        + (uint32_t)((lane >> 3) & 1) * 16;

    for (int kt = 0; kt < 4; kt++) {
        const int k0 = kt * 64;
#pragma unroll
        for (int it = 0; it < 8; it++) {
            const int idx = tid + it * 256;
            const int f = idx >> 3;
            const int c = idx & 7;
            const uint32_t so = f * VST + c * 16;
            const size_t go = (size_t)f * FF + k0 + c * 8;
            CP_ASYNC16(smem_base + GS_BH + so, (const char*)(g_WT_hi + go));
            CP_ASYNC16(smem_base + GS_BL + so, (const char*)(g_WT_lo + go));
        }
        CP_COMMIT();
#pragma unroll
        for (int t = 0; t < 4; t++) {
            const int idx = tid + t * 256;
            const int row = idx >> 4;
            const int cg = (idx & 15) * 4;
            float4 v = *(const float4*)&h[(size_t)(m0 + row) * FF + k0 + cg];
            __half hx = __float2half_rn(v.x), hy = __float2half_rn(v.y);
            __half hz = __float2half_rn(v.z), hw = __float2half_rn(v.w);
            __half2 hA = __halves2half2(hx, hy), hB = __halves2half2(hz, hw);
            __half2 lA = __halves2half2(__float2half_rn(v.x - __half2float(hx)),
                                        __float2half_rn(v.y - __half2float(hy)));
            __half2 lB = __halves2half2(__float2half_rn(v.z - __half2float(hz)),
                                        __float2half_rn(v.w - __half2float(hw)));
            uint2 hv, lv;
            hv.x = *reinterpret_cast<uint32_t*>(&hA);
            hv.y = *reinterpret_cast<uint32_t*>(&hB);
            lv.x = *reinterpret_cast<uint32_t*>(&lA);
            lv.y = *reinterpret_cast<uint32_t*>(&lB);
            *(uint2*)(smem + GS_AH + row * VST + cg * 2) = hv;
            *(uint2*)(smem + GS_AL + row * VST + cg * 2) = lv;
        }
        CP_WAIT0();
        __syncthreads();

#pragma unroll
        for (int ks = 0; ks < 4; ks++) {
            const uint32_t kb = ks * 32;
            uint32_t ah[2][4], al[2][4];
            ldsm_x4(ah[0], a_off_h + kb);
            ldsm_x4(ah[1], a_off_h + 16 * VST + kb);
            ldsm_x4(al[0], a_off_l + kb);
            ldsm_x4(al[1], a_off_l + 16 * VST + kb);
#pragma unroll
            for (int ntp = 0; ntp < 4; ntp++) {
                const uint32_t bo = b_row + ntp * 16 * VST + kb;
                uint32_t bh[4], bl[4];
                ldsm_x4(bh, smem_base + GS_BH + bo);
                ldsm_x4(bl, smem_base + GS_BL + bo);
#pragma unroll
                for (int mt = 0; mt < 2; mt++) {
                    mma16816(acc[mt][ntp * 2 + 0], ah[mt], &bh[0]);
                    mma16816(acc[mt][ntp * 2 + 1], ah[mt], &bh[2]);
                    mma16816(acc[mt][ntp * 2 + 0], ah[mt], &bl[0]);
                    mma16816(acc[mt][ntp * 2 + 1], ah[mt], &bl[2]);
                    mma16816(acc[mt][ntp * 2 + 0], al[mt], &bh[0]);
                    mma16816(acc[mt][ntp * 2 + 1], al[mt], &bh[2]);
                }
            }
        }
        __syncthreads();
    }

    const int ldq = lane >> 2;
    float* st = (float*)smem;
    float* s1p = (float*)(smem + GS_S1P);
    float* s2p = (float*)(smem + GS_S2P);

    if (tid < 64) { s1p[tid] = 0.f; s2p[tid] = 0.f; }
#pragma unroll
    for (int mt = 0; mt < 2; mt++) {
        const int r0 = m0w + mt * 16 + ldq;
#pragma unroll
        for (int nt = 0; nt < 8; nt++) {
            const int c0 = n0w + nt * 8 + (lane & 3) * 2;
            st[(c0 + 0) * TSTR + r0] = acc[mt][nt][0];
            st[(c0 + 1) * TSTR + r0] = acc[mt][nt][1];
            st[(c0 + 0) * TSTR + r0 + 8] = acc[mt][nt][2];
            st[(c0 + 1) * TSTR + r0 + 8] = acc[mt][nt][3];
        }
    }
    __syncthreads();

#pragma unroll
    for (int mt = 0; mt < 2; mt++) {
        const int r0 = m0w + mt * 16 + ldq;
        float s1x = 0.f, s1y = 0.f, s2x = 0.f, s2y = 0.f;
#pragma unroll
        for (int nt = 0; nt < 8; nt++) {
            const int c0 = n0w + nt * 8 + (lane & 3) * 2;
            float a10 = aVec[c0], a11 = aVec[c0 + 1];
            float a20 = aVec[FF + c0], a21 = aVec[FF + c0 + 1];
            s1x += acc[mt][nt][0] * a10 + acc[mt][nt][1] * a11;
            s1y += acc[mt][nt][2] * a10 + acc[mt][nt][3] * a11;
            s2x += acc[mt][nt][0] * a20 + acc[mt][nt][1] * a21;
            s2y += acc[mt][nt][2] * a20 + acc[mt][nt][3] * a21;
        }
#pragma unroll
        for (int o = 1; o <= 2; o <<= 1) {
            s1x += __shfl_xor_sync(0xffffffffu, s1x, o);
            s1y += __shfl_xor_sync(0xffffffffu, s1y, o);
            s2x += __shfl_xor_sync(0xffffffffu, s2x, o);
            s2y += __shfl_xor_sync(0xffffffffu, s2y, o);
        }
        if ((lane & 3) == 0) {
            atomicAdd(&s1p[r0], s1x);
            atomicAdd(&s1p[r0 + 8], s1y);
            atomicAdd(&s2p[r0], s2x);
            atomicAdd(&s2p[r0 + 8], s2y);
        }
    }
    __syncthreads();

    __half* whtB = g_WhT + (size_t)b * FF * NN + n_in_b;
#pragma unroll
    for (int t = 0; t < 16; t++) {
        const int idx = tid + t * 256;
        const int f = idx >> 4;
        const int m4 = (idx & 15) * 4;
        float v0 = st[f * TSTR + m4 + 0];
        float v1 = st[f * TSTR + m4 + 1];
        float v2 = st[f * TSTR + m4 + 2];
        float v3 = st[f * TSTR + m4 + 3];
        __half2 hA = __floats2half2_rn(v0, v1);
        __half2 hB = __floats2half2_rn(v2, v3);
        uint2 hv;
        hv.x = *reinterpret_cast<uint32_t*>(&hA);
        hv.y = *reinterpret_cast<uint32_t*>(&hB);
        *(uint2*)(whtB + (size_t)f * NN + m4) = hv;
    }
    if (tid < 64) {
        g_s1[m0 + tid] = s1p[tid];
        g_s2[m0 + tid] = s2p[tid];
    }
}

// ============================================================
// Kernel 2: per-batch max of s2
// ============================================================
__global__ __launch_bounds__(256) void s2max_kernel()
{
    __shared__ float red[256];
    const int b = blockIdx.x;
    float m = -1e30f;
    for (int i = threadIdx.x; i < NN; i += 256) m = fmaxf(m, g_s2[b * NN + i]);
    red[threadIdx.x] = m;
    __syncthreads();
#pragma unroll
    for (int s = 128; s; s >>= 1) {
        if (threadIdx.x < s) red[threadIdx.x] = fmaxf(red[threadIdx.x], red[threadIdx.x + s]);
        __syncthreads();
    }
    if (threadIdx.x == 0) g_s2max[b] = red[0];
}

// ============================================================
// Kernel 3: fused masked softmax + PV, fp16 single-pass V,
// TI=64, KJ=64, V double-buffered, R6 phase structure, 2 CTAs/SM
// ============================================================
#define TI 64
#define KJ 64
#define NJ (NN / KJ)

#define SM_VH0 0
#define SM_VH1 (SM_VH0 + FF * VST)          // 36864
#define SM_P   (SM_VH1 + FF * VST)          // 73728
#define SM_ZS  (SM_P + TI * VST)            // 82944
#define SM_TOTAL (SM_ZS + TI * 4)           // 83200

__global__ __launch_bounds__(256, 2) void attn_mma_kernel(
    const int* __restrict__ adj, float* __restrict__ out)
{
    extern __shared__ char smem[];
    const uint32_t smem_base = smem_u32(smem);
    const int tid = threadIdx.x;
    const int wid = tid >> 5;
    const int lane = tid & 31;
    const int b = blockIdx.y;
    const int i0 = blockIdx.x * TI;

    const int m0w = (wid & 1) * 32;
    const int n0w = (wid >> 1) * 64;

    // P-compute mapping: thread -> (row r, 16 j's at jbase)
    const int r = tid >> 2;
    const int jbase = (tid & 3) * 16;

    const float s1v = g_s1[b * NN + i0 + r];
    const float ms2 = g_s2max[b];
    const float tpre = s1v + ms2;
    const float mi = tpre > 0.f ? tpre : ALPHA * tpre;
    float zloc = 0.f;

    const int* __restrict__ adjR = adj + ((size_t)b * NN + i0 + r) * NN;
    const float* __restrict__ s2B = g_s2 + b * NN;
    const __half* __restrict__ wht = g_WhT + (size_t)b * FF * NN;

    float acc[2][8][4];
#pragma unroll
    for (int mt = 0; mt < 2; mt++)
#pragma unroll
        for (int nt = 0; nt < 8; nt++)
#pragma unroll
            for (int q = 0; q < 4; q++) acc[mt][nt][q] = 0.f;

    const uint32_t a_off = smem_base + SM_P
        + (uint32_t)(m0w + ((lane >> 3) & 1) * 8 + (lane & 7)) * VST
        + (uint32_t)(lane >> 4) * 16;
    const uint32_t b_row = (uint32_t)(n0w + ((lane >> 4) & 1) * 8 + (lane & 7)) * VST
        + (uint32_t)((lane >> 3) & 1) * 16;

    // V staging: 256 f-rows x 64 j fp16 = 2048 x 16B chunks -> 8/thread
    const int vf = tid >> 3;
    const int vc = tid & 7;

    // prologue: issue V[0], prefetch adj[0]
    {
#pragma unroll
        for (int it = 0; it < 8; it++) {
            const int f = vf + it * 32;
            const uint32_t so = f * VST + vc * 16;
            const size_t go = (size_t)f * NN + 0 + vc * 8;
            CP_ASYNC16(smem_base + SM_VH0 + so, (const char*)(wht + go));
        }
        CP_COMMIT();
    }
    int4 am_pf[4];
#pragma unroll
    for (int g = 0; g < 4; g++)
        am_pf[g] = *(const int4*)&adjR[jbase + g * 4];

    for (int jt = 0; jt < NJ; jt++) {
        const int j0 = jt * KJ;
        const uint32_t vh = (jt & 1) ? SM_VH1 : SM_VH0;
        const uint32_t vhn = (jt & 1) ? SM_VH0 : SM_VH1;

        // ---- compute P tile [64 x 64] fp16 (P buffer free: barrier at loop end) ----
#pragma unroll
        for (int g = 0; g < 4; g++) {
            const int j = j0 + jbase + g * 4;
            int4 am = am_pf[g];
            float4 s2q = *(const float4*)&s2B[j];
            float p0, p1, p2, p3, ev;
            ev = s1v + s2q.x; ev = ev > 0.f ? ev : ALPHA * ev;
            p0 = (am.x > 0) ? __expf(ev - mi) : 0.f;
            ev = s1v + s2q.y; ev = ev > 0.f ? ev : ALPHA * ev;
            p1 = (am.y > 0) ? __expf(ev - mi) : 0.f;
            ev = s1v + s2q.z; ev = ev > 0.f ? ev : ALPHA * ev;
            p2 = (am.z > 0) ? __expf(ev - mi) : 0.f;
            ev = s1v + s2q.w; ev = ev > 0.f ? ev : ALPHA * ev;
            p3 = (am.w > 0) ? __expf(ev - mi) : 0.f;
            zloc += (p0 + p1) + (p2 + p3);

            __half2 hA = __floats2half2_rn(p0, p1);
            __half2 hB = __floats2half2_rn(p2, p3);
            uint2 hv;
            hv.x = *reinterpret_cast<uint32_t*>(&hA);
            hv.y = *reinterpret_cast<uint32_t*>(&hB);
            *(uint2*)(smem + SM_P + r * VST + (jbase + g * 4) * 2) = hv;
        }

        // ---- wait V[jt]; make P + V visible ----
        CP_WAIT0();
        __syncthreads();

        // ---- issue V[jt+1] into other buffer (covered by MMA below) ----
        if (jt + 1 < NJ) {
            const int jn = j0 + KJ;
#pragma unroll
            for (int it = 0; it < 8; it++) {
                const int f = vf + it * 32;
                const uint32_t so = f * VST + vc * 16;
                const size_t go = (size_t)f * NN + jn + vc * 8;
                CP_ASYNC16(smem_base + vhn + so, (const char*)(wht + go));
            }
            CP_COMMIT();
            // prefetch adj[jt+1] (latency spans MMA)
#pragma unroll
            for (int g = 0; g < 4; g++)
                am_pf[g] = *(const int4*)&adjR[jn + jbase + g * 4];
        }

        // ---- HMMA: acc += P * V ----
#pragma unroll
        for (int ks = 0; ks < 4; ks++) {
            const uint32_t kb = ks * 32;
            uint32_t ah[2][4];
            ldsm_x4(ah[0], a_off + kb);
            ldsm_x4(ah[1], a_off + 16 * VST + kb);
#pragma unroll
            for (int ntp = 0; ntp < 4; ntp++) {
                const uint32_t bo = b_row + ntp * 16 * VST + kb;
                uint32_t bh[4];
                ldsm_x4(bh, smem_base + vh + bo);
#pragma unroll
                for (int mt = 0; mt < 2; mt++) {
                    mma16816(acc[mt][ntp * 2 + 0], ah[mt], &bh[0]);
                    mma16816(acc[mt][ntp * 2 + 1], ah[mt], &bh[2]);
                }
            }
        }
        __syncthreads();   // P buffer + V[jt] buffer reusable
    }

    // ---- Z reduction (quads share a row) ----
    zloc += __shfl_xor_sync(0xffffffffu, zloc, 1);
    zloc += __shfl_xor_sync(0xffffffffu, zloc, 2);
    if ((tid & 3) == 0) *(float*)(smem + SM_ZS + r * 4) = zloc;
    __syncthreads();

    // ---- epilogue: out = acc / Z ----
    const float* Zs = (const float*)(smem + SM_ZS);
    const int ldq = lane >> 2;
#pragma unroll
    for (int mt = 0; mt < 2; mt++) {
        const int row0 = m0w + mt * 16 + ldq;
        const float rz0 = 1.f / Zs[row0];
        const float rz1 = 1.f / Zs[row0 + 8];
        float* __restrict__ o0 = out + ((size_t)b * NN + i0 + row0) * FF;
        float* __restrict__ o1 = o0 + 8 * FF;
#pragma unroll
        for (int nt = 0; nt < 8; nt++) {
            const int col = n0w + nt * 8 + (lane & 3) * 2;
            float2 v0 = make_float2(acc[mt][nt][0] * rz0, acc[mt][nt][1] * rz0);
            float2 v1 = make_float2(acc[mt][nt][2] * rz1, acc[mt][nt][3] * rz1);
            *(float2*)&o0[col] = v0;
            *(float2*)&o1[col] = v1;
        }
    }
}

// ============================================================
// launch
// ============================================================
extern "C" void kernel_launch(void* const* d_in, const int* in_sizes, int n_in,
                              void* d_out, int out_size)
{
    const float* h   = (const float*)d_in[0];
    const int*   adj = (const int*)d_in[1];
    const float* W   = (const float*)d_in[2];
    const float* a   = (const float*)d_in[3];
    float* out = (float*)d_out;

    cudaFuncSetAttribute(gemm_fused_kernel,
                         cudaFuncAttributeMaxDynamicSharedMemorySize, GS_TOTAL);
    cudaFuncSetAttribute(attn_mma_kernel,
                         cudaFuncAttributeMaxDynamicSharedMemorySize, SM_TOTAL);

    dim3 g0(FF / 32, FF / 32);
    prep_wt_kernel<<<g0, 256>>>(W);

    gemm_fused_kernel<<<BB * NN / 64, 256, GS_TOTAL>>>(h, a);

    s2max_kernel<<<BB, 256>>>();

    dim3 g4(NN / TI, BB);
    attn_mma_kernel<<<g4, 256, SM_TOTAL>>>(adj, out);
}